// round 16
// baseline (speedup 1.0000x reference)
#include <cuda_runtime.h>
#include <cstdint>

#define SEQ 4096
#define HID 256
#define EMB 256

// ---------------------------------------------------------------------------
// Scratch: x_proj[t][j] (4096 x 256 fp32 = 4 MB). Device global (no alloc).
// ---------------------------------------------------------------------------
__device__ float g_xproj[SEQ * HID];

// ---------------------------------------------------------------------------
// Phase 1: x_proj = embedding[tokens] @ wx_w.T + wx_b  (~25us)
// ---------------------------------------------------------------------------
#define TOK_PER_BLK 16

__global__ __launch_bounds__(256) void xproj_kernel(
    const int* __restrict__ tokens,
    const float* __restrict__ embedding,
    const float* __restrict__ wx_w,
    const float* __restrict__ wx_b)
{
    __shared__ float emb_sm[TOK_PER_BLK * EMB];
    const int tid = threadIdx.x;
    const int t0  = blockIdx.x * TOK_PER_BLK;

    #pragma unroll
    for (int i = 0; i < TOK_PER_BLK; i++) {
        long tok = (long)tokens[t0 + i];
        emb_sm[i * EMB + tid] = embedding[tok * (long)EMB + tid];
    }
    __syncthreads();

    float acc[TOK_PER_BLK];
    #pragma unroll
    for (int i = 0; i < TOK_PER_BLK; i++) acc[i] = 0.f;

    const float4* wrow = reinterpret_cast<const float4*>(wx_w + tid * EMB);
    #pragma unroll 4
    for (int k4 = 0; k4 < EMB / 4; k4++) {
        float4 w = wrow[k4];
        #pragma unroll
        for (int i = 0; i < TOK_PER_BLK; i++) {
            float4 e = *reinterpret_cast<const float4*>(&emb_sm[i * EMB + 4 * k4]);
            acc[i] += w.x * e.x + w.y * e.y + w.z * e.z + w.w * e.w;
        }
    }

    const float b = wx_b[tid];
    #pragma unroll
    for (int i = 0; i < TOK_PER_BLK; i++)
        g_xproj[(t0 + i) * HID + tid] = acc[i] + b;
}

// ---------------------------------------------------------------------------
// Phase 2: serial recurrence, 8-CTA cluster, minimal-chain partial exchange.
// (Champion configuration — R10, best measured 2228.6 us.)
//
// CTA r owns h components [r*32, r*32+32); its k-slice for every dot is the
// same range, so h NEVER crosses the cluster. One thread per GLOBAL output
// (o = tid, 256 threads): 16 packed f32x2 FMAs over this CTA's 32-k slice.
//   - o owned here (exactly warp 'rank'): deposit own partial into the inbox
//     row, poll the full 8-slot row with two volatile 16B loads until no
//     sentinel remains, sum 8, + bias + x_proj, sigmoid, store h, re-arm row
//     with two STS.128 of sentinel.
//   - o owned elsewhere (7 warps): one st.shared::cluster of the partial into
//     owner CTA's inbox[cur][(o&31)*8 + rank].
// Warps are pure-owner or pure-sender -> zero divergence.
// One __syncthreads per step: publishes hbuf[nxt], drains the owner's
// sentinel re-arm, closes reads of hbuf[cur].
//
// Sentinel protocol (distance-2, proven R3/R6/R7/R8/R10/R12/R14): inbox
// idles at 0xFFFFFFFF (NaN bit-pattern finite dots never produce). Owner
// re-arms consumed words before its end-of-step bar (BAR.SYNC drains STS);
// its CTA's senders ship step-t+1 partials after that bar; every other
// CTA's owner consumes those before its own t+1 bar; their senders' t+2
// writes into the re-armed row are causally after that -> re-arm always
// precedes rewrite.
// ---------------------------------------------------------------------------
#define NCTA 8
#define THREADS2 256
#define SLICE 32          // outputs (and k's) per CTA
#define SENTB 0xFFFFFFFFu
#define INBOX_WORDS 256   // 32 outputs x 8 sender slots (one buffer)

__device__ __forceinline__ uint32_t smem_u32(const void* p) {
    uint32_t a;
    asm("{ .reg .u64 t; cvta.to.shared.u64 t, %1; cvt.u32.u64 %0, t; }"
        : "=r"(a) : "l"(p));
    return a;
}
__device__ __forceinline__ uint32_t mapa_rank(uint32_t a, uint32_t rank) {
    uint32_t r;
    asm("mapa.shared::cluster.u32 %0, %1, %2;" : "=r"(r) : "r"(a), "r"(rank));
    return r;
}
__device__ __forceinline__ void st_remote_f32(uint32_t a, float v) {
    asm volatile("st.shared::cluster.f32 [%0], %1;" :: "r"(a), "f"(v) : "memory");
}
__device__ __forceinline__ void fma2(unsigned long long& acc,
                                     unsigned long long a, unsigned long long b) {
    asm("fma.rn.f32x2 %0, %1, %2, %0;" : "+l"(acc) : "l"(a), "l"(b));
}
__device__ __forceinline__ unsigned long long pack2(float x, float y) {
    unsigned long long v;
    asm("mov.b64 %0, {%1, %2};" : "=l"(v) : "f"(x), "f"(y));
    return v;
}
__device__ __forceinline__ void unpack2(unsigned long long v, float& x, float& y) {
    asm("mov.b64 {%0, %1}, %2;" : "=f"(x), "=f"(y) : "l"(v));
}
// volatile 16B smem load / store (for inbox row poll + re-arm)
__device__ __forceinline__ void ldsv4(uint32_t addr, unsigned& a, unsigned& b,
                                      unsigned& c, unsigned& d) {
    asm volatile("ld.volatile.shared.v4.u32 {%0,%1,%2,%3}, [%4];"
                 : "=r"(a), "=r"(b), "=r"(c), "=r"(d) : "r"(addr));
}
__device__ __forceinline__ void stsv4(uint32_t addr, unsigned a, unsigned b,
                                      unsigned c, unsigned d) {
    asm volatile("st.volatile.shared.v4.u32 [%0], {%1,%2,%3,%4};"
                 :: "r"(addr), "r"(a), "r"(b), "r"(c), "r"(d) : "memory");
}
__device__ __forceinline__ void stsv1(uint32_t addr, unsigned v) {
    asm volatile("st.volatile.shared.u32 [%0], %1;"
                 :: "r"(addr), "r"(v) : "memory");
}

__global__ __launch_bounds__(THREADS2, 1) __cluster_dims__(NCTA, 1, 1)
void rnn_kernel(const float* __restrict__ wh_w,
                const float* __restrict__ wh_b,
                float* __restrict__ out)
{
    __shared__ __align__(16) float    hbuf[2][SLICE];        // own h slice only
    __shared__ __align__(16) unsigned inbox[2][INBOX_WORDS]; // [o&31][sender]

    const int tid = threadIdx.x;
    uint32_t rank; asm("mov.u32 %0, %%cluster_ctarank;" : "=r"(rank));

    const int o    = tid;            // GLOBAL output index 0..255
    const int own  = o >> 5;         // owner CTA (= warp id) of output o
    const bool owner = (own == (int)rank);

    // Register-resident packed weights: wh_w[o][rank*32 .. rank*32+32)
    unsigned long long w[SLICE / 2];
    {
        const float* row = wh_w + o * HID + (int)rank * SLICE;
        #pragma unroll
        for (int i = 0; i < SLICE / 2; i++)
            w[i] = pack2(row[2 * i], row[2 * i + 1]);
    }

    // Init: h0 = 0 (own slice); both inbox buffers armed with sentinel.
    if (tid < SLICE) { hbuf[0][tid] = 0.f; }
    reinterpret_cast<unsigned*>(inbox)[tid]            = SENTB;
    reinterpret_cast<unsigned*>(inbox)[tid + THREADS2] = SENTB;

    float bias = 0.f, xp_cur = 0.f, hn = 0.f;
    if (owner) {
        bias   = wh_b[o];
        xp_cur = g_xproj[o];
    }
    __syncthreads();
    // One-time: all CTAs' sentinels visible before any remote store.
    asm volatile("barrier.cluster.arrive.aligned;" ::: "memory");
    asm volatile("barrier.cluster.wait.aligned;"   ::: "memory");

    // Sender: remote address of owner CTA's inbox slot [buf0][(o&31)*8 + rank]
    uint32_t dst = 0;
    if (!owner)
        dst = mapa_rank(smem_u32(&inbox[0][0]), (uint32_t)own)
            + (uint32_t)(((o & 31) << 3) + (int)rank) * 4u;
    // Owner: local base of its inbox row (32B, 16B-aligned)
    const uint32_t rowbase = smem_u32(&inbox[0][(o & 31) << 3]);
    const uint32_t BUFB = INBOX_WORDS * 4u;   // bytes between inbox buffers

    for (int t = 0; t < SEQ; t++) {
        const int cur = t & 1;
        const int nxt = cur ^ 1;

        float xp_next = 0.f;
        if (owner && (t + 1 < SEQ))
            xp_next = __ldg(&g_xproj[(t + 1) * HID + o]);

        // ---- 32-MAC partial over own slice (full-broadcast LDS) ----
        const ulonglong2* h2 =
            reinterpret_cast<const ulonglong2*>(&hbuf[cur][0]);
        unsigned long long a0 = 0ull, a1 = 0ull;
        #pragma unroll
        for (int i = 0; i < 8; i++) {
            ulonglong2 hv = h2[i];
            fma2(a0, w[2 * i],     hv.x);
            fma2(a1, w[2 * i + 1], hv.y);
        }
        float x0, y0, x1, y1;
        unpack2(a0, x0, y0); unpack2(a1, x1, y1);
        float s = (x0 + y0) + (x1 + y1);

        if (!owner) {
            // ship partial straight to the owner CTA
            st_remote_f32(dst + (uint32_t)cur * BUFB, s);
        } else {
            // deposit own partial, then poll the whole 8-slot row (2x16B)
            const uint32_t rb = rowbase + (uint32_t)cur * BUFB;
            stsv1(rb + (uint32_t)rank * 4u, __float_as_uint(s));
            unsigned v0, v1, v2, v3, v4, v5, v6, v7;
            for (;;) {
                ldsv4(rb,      v0, v1, v2, v3);
                ldsv4(rb + 16, v4, v5, v6, v7);
                if (v0 != SENTB && v1 != SENTB && v2 != SENTB && v3 != SENTB &&
                    v4 != SENTB && v5 != SENTB && v6 != SENTB && v7 != SENTB)
                    break;
            }
            // re-arm the row for step t+2
            stsv4(rb,      SENTB, SENTB, SENTB, SENTB);
            stsv4(rb + 16, SENTB, SENTB, SENTB, SENTB);

            float v = ((__uint_as_float(v0) + __uint_as_float(v1)) +
                       (__uint_as_float(v2) + __uint_as_float(v3))) +
                      ((__uint_as_float(v4) + __uint_as_float(v5)) +
                       (__uint_as_float(v6) + __uint_as_float(v7)));
            float z = v + bias + xp_cur;
            hn = __fdividef(1.f, 1.f + __expf(-z));
            hbuf[nxt][o & 31] = hn;
            xp_cur = xp_next;
        }
        __syncthreads();  // publish hbuf[nxt]; drain re-arm; reads of [cur] done
    }

    if (owner) out[o] = hn;
}

// ---------------------------------------------------------------------------
// kernel_launch
//   d_in: [0] tokens i32[4096], [1] embedding f32[128000*256],
//         [2] wx_w f32[256*256], [3] wx_b f32[256],
//         [4] wh_w f32[256*256], [5] wh_b f32[256]
// ---------------------------------------------------------------------------
extern "C" void kernel_launch(void* const* d_in, const int* in_sizes, int n_in,
                              void* d_out, int out_size)
{
    const int*   tokens    = (const int*)d_in[0];
    const float* embedding = (const float*)d_in[1];
    const float* wx_w      = (const float*)d_in[2];
    const float* wx_b      = (const float*)d_in[3];
    const float* wh_w      = (const float*)d_in[4];
    const float* wh_b      = (const float*)d_in[5];
    float*       out       = (float*)d_out;

    xproj_kernel<<<SEQ / TOK_PER_BLK, 256>>>(tokens, embedding, wx_w, wx_b);
    rnn_kernel<<<NCTA, THREADS2>>>(wh_w, wh_b, out);
}

// round 17
// speedup vs baseline: 1.1508x; 1.1508x over previous
#include <cuda_runtime.h>
#include <cstdint>

#define SEQ 4096
#define HID 256
#define EMB 256

// ---------------------------------------------------------------------------
// Scratch: x_proj[t][j] (4096 x 256 fp32 = 4 MB). Device global (no alloc).
// ---------------------------------------------------------------------------
__device__ float g_xproj[SEQ * HID];

// ---------------------------------------------------------------------------
// Phase 1: x_proj = embedding[tokens] @ wx_w.T + wx_b  (~25us)
// ---------------------------------------------------------------------------
#define TOK_PER_BLK 16

__global__ __launch_bounds__(256) void xproj_kernel(
    const int* __restrict__ tokens,
    const float* __restrict__ embedding,
    const float* __restrict__ wx_w,
    const float* __restrict__ wx_b)
{
    __shared__ float emb_sm[TOK_PER_BLK * EMB];
    const int tid = threadIdx.x;
    const int t0  = blockIdx.x * TOK_PER_BLK;

    #pragma unroll
    for (int i = 0; i < TOK_PER_BLK; i++) {
        long tok = (long)tokens[t0 + i];
        emb_sm[i * EMB + tid] = embedding[tok * (long)EMB + tid];
    }
    __syncthreads();

    float acc[TOK_PER_BLK];
    #pragma unroll
    for (int i = 0; i < TOK_PER_BLK; i++) acc[i] = 0.f;

    const float4* wrow = reinterpret_cast<const float4*>(wx_w + tid * EMB);
    #pragma unroll 4
    for (int k4 = 0; k4 < EMB / 4; k4++) {
        float4 w = wrow[k4];
        #pragma unroll
        for (int i = 0; i < TOK_PER_BLK; i++) {
            float4 e = *reinterpret_cast<const float4*>(&emb_sm[i * EMB + 4 * k4]);
            acc[i] += w.x * e.x + w.y * e.y + w.z * e.z + w.w * e.w;
        }
    }

    const float b = wx_b[tid];
    #pragma unroll
    for (int i = 0; i < TOK_PER_BLK; i++)
        g_xproj[(t0 + i) * HID + tid] = acc[i] + b;
}

// ---------------------------------------------------------------------------
// Phase 2: serial recurrence, 8-CTA cluster, SPMD redundant-h (no bar, no
// publish hop). CTA r owns h slice [r*32, r*32+32); every warp of CTA r
// computes the WHOLE slice itself each step (lane L computes h[r*32+L] from
// inbox row L), stores it to a warp-PRIVATE staging row, __syncwarp, dots,
// ships. No __syncthreads in the loop; warps couple only through inbox data.
//
// Per thread (o = tid = wid*32+lane):
//   dot output  o        = wid*32+lane  (destination CTA = wid), weights
//                          wh_w[o][rank*32 .. +32) in 16 packed f32x2 regs
//   h output    rank*32+lane            (bias_h, xp per-lane)
// Iteration t (t = 1..SEQ-1), buffer b = t&7 (DEPTH-8 inbox):
//   (a) t>=4: lane L re-arms inbox[(t-3)&7][row L][slot wid] = SENT
//   (b) dot over stage[wid][0..31] (h_t)
//   (c) ship partial: warp wid -> CTA wid's inbox[b][row lane][slot rank]
//       (wid==rank: plain local volatile STS)
//   (d) poll row lane of inbox[b] (2x16B volatile) until 8 non-sentinel;
//       h_{t+1}[rank*32+lane] = sigmoid(xp_t + bias + sum8);
//       stage[wid][lane] = h; __syncwarp
//
// Ordering proofs (all chains = alternating DSMEM round trips, >=400cyc/hop;
// STS completion ~4cyc swamped):
//  * REARM-AFTER-READS: warp j at (a)@t implies (d)@t-1 done, which consumed
//    CTA m's warp-rank ship (c)@t-1 <= CTA m (d)@t-2 <= our warp m (c)@t-2,
//    which program-follows warp m's (d)@t-3 ... >= reads@t-3 of buffer
//    (t-3)&7. All local warps' reads of that buffer precede the re-arm.
//  * WRITE-AFTER-REARM: writer of our slot j (CTA j's warp rank) at (c)@t+8
//    <= CTA j (d)@t+7 <= OUR warp j (c)@t+7, which program-follows our warp
//    j's (a)@t+5 re-arm of this buffer. Slot-j re-arm by warp j makes this
//    chain exist for every slot.
//  * NO-STALE-READ: any warp m's poll (d)@t of buffer b is causally after
//    our warp j (c)@t-2 (chain: (d)@t needs h_t = (d)@t-1 partials <= CTA j
//    warp-rank (c)@t-1 <= CTA j (d)@t-2... actually via CTA x: <= our warp
//    j (c)@t-2), which program-follows warp j's (a)@t-5 re-arm of buffer b.
//    So polls see SENT or the fresh value, never the t-8 leftover.
// Sentinel 0xFFFFFFFF is a NaN bit pattern finite dots never produce
// (proven R8/R10/R12/R14/R16).
// ---------------------------------------------------------------------------
#define NCTA 8
#define THREADS2 256
#define SLICE 32
#define SENTB 0xFFFFFFFFu
#define DEPTH 8
#define INBOX_WORDS 256            // 32 rows x 8 slots per buffer
#define BUF_BYTES (INBOX_WORDS * 4)

__device__ __forceinline__ uint32_t smem_u32(const void* p) {
    uint32_t a;
    asm("{ .reg .u64 t; cvta.to.shared.u64 t, %1; cvt.u32.u64 %0, t; }"
        : "=r"(a) : "l"(p));
    return a;
}
__device__ __forceinline__ uint32_t mapa_rank(uint32_t a, uint32_t rank) {
    uint32_t r;
    asm("mapa.shared::cluster.u32 %0, %1, %2;" : "=r"(r) : "r"(a), "r"(rank));
    return r;
}
__device__ __forceinline__ void st_remote_f32(uint32_t a, float v) {
    asm volatile("st.shared::cluster.f32 [%0], %1;" :: "r"(a), "f"(v) : "memory");
}
__device__ __forceinline__ void fma2(unsigned long long& acc,
                                     unsigned long long a, unsigned long long b) {
    asm("fma.rn.f32x2 %0, %1, %2, %0;" : "+l"(acc) : "l"(a), "l"(b));
}
__device__ __forceinline__ unsigned long long pack2(float x, float y) {
    unsigned long long v;
    asm("mov.b64 %0, {%1, %2};" : "=l"(v) : "f"(x), "f"(y));
    return v;
}
__device__ __forceinline__ void unpack2(unsigned long long v, float& x, float& y) {
    asm("mov.b64 {%0, %1}, %2;" : "=f"(x), "=f"(y) : "l"(v));
}
__device__ __forceinline__ void ldsv4(uint32_t addr, unsigned& a, unsigned& b,
                                      unsigned& c, unsigned& d) {
    asm volatile("ld.volatile.shared.v4.u32 {%0,%1,%2,%3}, [%4];"
                 : "=r"(a), "=r"(b), "=r"(c), "=r"(d) : "r"(addr));
}
__device__ __forceinline__ void stsv1(uint32_t addr, unsigned v) {
    asm volatile("st.volatile.shared.u32 [%0], %1;"
                 :: "r"(addr), "r"(v) : "memory");
}

__global__ __launch_bounds__(THREADS2, 1) __cluster_dims__(NCTA, 1, 1)
void rnn_kernel(const float* __restrict__ wh_w,
                const float* __restrict__ wh_b,
                float* __restrict__ out)
{
    __shared__ __align__(16) unsigned inbox[DEPTH][INBOX_WORDS]; // 8 KB
    __shared__ __align__(16) float    stage[NCTA][SLICE];        // warp-private h

    const int tid  = threadIdx.x;
    uint32_t rank; asm("mov.u32 %0, %%cluster_ctarank;" : "=r"(rank));

    const int o    = tid;            // dot output (destination CTA = o>>5)
    const int wid  = o >> 5;
    const int lane = o & 31;
    const bool owner = (wid == (int)rank);
    const int hidx = (int)rank * SLICE + lane;   // this lane's h output

    // Weights for dot output o over our k-slice
    unsigned long long w[SLICE / 2];
    {
        const float* row = wh_w + o * HID + (int)rank * SLICE;
        #pragma unroll
        for (int i = 0; i < SLICE / 2; i++)
            w[i] = pack2(row[2 * i], row[2 * i + 1]);
    }
    const float bias_h = wh_b[hidx];

    // Init: all DEPTH inbox buffers armed with sentinel (2048 words).
    {
        unsigned* flat = &inbox[0][0];
        #pragma unroll
        for (int i = 0; i < DEPTH; i++) flat[tid + i * THREADS2] = SENTB;
    }

    // Prologue: h1 = sigmoid(xp0 + b) (h0 = 0); every warp stages its copy.
    float hn = __fdividef(1.f, 1.f + __expf(-(g_xproj[hidx] + bias_h)));
    stage[wid][lane] = hn;

    __syncthreads();
    // One-time: all CTAs' sentinels visible before any remote store.
    asm volatile("barrier.cluster.arrive.aligned;" ::: "memory");
    asm volatile("barrier.cluster.wait.aligned;"   ::: "memory");

    const uint32_t inbase = smem_u32(&inbox[0][0]);
    // Sender: remote base of CTA 'wid' inbox [row lane][slot rank]
    uint32_t dstb = 0;
    if (!owner)
        dstb = mapa_rank(inbase, (uint32_t)wid)
             + (uint32_t)(((lane) << 3) + (int)rank) * 4u;
    // Local addresses
    const uint32_t depb = inbase + (uint32_t)((lane << 3) + (int)rank) * 4u; // owner deposit
    const uint32_t rowb = inbase + (uint32_t)(lane << 5);                    // my poll row
    const uint32_t reab = inbase + (uint32_t)((lane << 3) + wid) * 4u;       // my re-arm slot
    const uint32_t stg  = smem_u32(&stage[wid][0]);

    for (int t = 1; t < SEQ; t++) {
        const uint32_t boff = (uint32_t)(t & 7) * BUF_BYTES;

        // (a) re-arm slot 'wid' of buffer (t-3)&7 (see proofs above)
        if (t >= 4)
            stsv1(reab + (uint32_t)((t - 3) & 7) * BUF_BYTES, SENTB);

        // prefetch xp_t for the (d) stage (hidden behind dot + flight)
        const float xp_t = __ldg(&g_xproj[t * HID + hidx]);

        // (b) dot over stage[wid] = h_t
        unsigned long long a0 = 0ull, a1 = 0ull;
        {
            const ulonglong2* h2 = reinterpret_cast<const ulonglong2*>(
                &stage[wid][0]);
            #pragma unroll
            for (int i = 0; i < 8; i++) {
                ulonglong2 hv = h2[i];
                fma2(a0, w[2 * i],     hv.x);
                fma2(a1, w[2 * i + 1], hv.y);
            }
        }
        float x0, y0, x1, y1;
        unpack2(a0, x0, y0); unpack2(a1, x1, y1);
        float s = (x0 + y0) + (x1 + y1);

        // (c) ship partial for output o into CTA wid's inbox
        if (owner) stsv1(depb + boff, __float_as_uint(s));
        else       st_remote_f32(dstb + boff, s);

        // (d) poll my row; compute h_{t+1} for output hidx; restage
        const uint32_t rb = rowb + boff;
        unsigned v0, v1, v2, v3, v4, v5, v6, v7;
        for (;;) {
            ldsv4(rb,      v0, v1, v2, v3);
            ldsv4(rb + 16, v4, v5, v6, v7);
            if (v0 != SENTB && v1 != SENTB && v2 != SENTB && v3 != SENTB &&
                v4 != SENTB && v5 != SENTB && v6 != SENTB && v7 != SENTB)
                break;
        }
        float v = ((__uint_as_float(v0) + __uint_as_float(v1)) +
                   (__uint_as_float(v2) + __uint_as_float(v3))) +
                  ((__uint_as_float(v4) + __uint_as_float(v5)) +
                   (__uint_as_float(v6) + __uint_as_float(v7)));
        float z = v + bias_h + xp_t;
        hn = __fdividef(1.f, 1.f + __expf(-z));
        stage[wid][lane] = hn;
        __syncwarp();      // warp-private staging ready for (b) of t+1
    }

    // Every warp holds h_SEQ redundantly; warp 0 writes the CTA's slice.
    if (wid == 0) out[hidx] = hn;
}

// ---------------------------------------------------------------------------
// kernel_launch
//   d_in: [0] tokens i32[4096], [1] embedding f32[128000*256],
//         [2] wx_w f32[256*256], [3] wx_b f32[256],
//         [4] wh_w f32[256*256], [5] wh_b f32[256]
// ---------------------------------------------------------------------------
extern "C" void kernel_launch(void* const* d_in, const int* in_sizes, int n_in,
                              void* d_out, int out_size)
{
    const int*   tokens    = (const int*)d_in[0];
    const float* embedding = (const float*)d_in[1];
    const float* wx_w      = (const float*)d_in[2];
    const float* wx_b      = (const float*)d_in[3];
    const float* wh_w      = (const float*)d_in[4];
    const float* wh_b      = (const float*)d_in[5];
    float*       out       = (float*)d_out;

    xproj_kernel<<<SEQ / TOK_PER_BLK, 256>>>(tokens, embedding, wx_w, wx_b);
    rnn_kernel<<<NCTA, THREADS2>>>(wh_w, wh_b, out);
}